// round 16
// baseline (speedup 1.0000x reference)
#include <cuda_runtime.h>
#include <cuda_bf16.h>
#include <cstddef>
#include <cstdint>

#define cN 50000
#define cE 1600000
#define cD 128
#define SLOPE 0.01f

#define GEMM_BLOCKS 391   // (cN + 127) / 128
#define DEG_BLOCKS 1563   // (cE/4 + 255) / 256
#define U_BLOCKS 17       // ((cD+1)*32 + 255) / 256
#define CSR2_BLOCKS 148   // one looper per SM; ids 0..147 land one-per-SM

// ---------------- scratch (static device globals; no allocation) ----------------
__device__ int   g_outdeg[cN];      // zeroed by csr loopers each call (zero-init first call)
__device__ int   g_indeg[cN];
__device__ int   g_offsets[cN + 4];
__device__ int   g_cursor[cN];
__device__ int   g_blocksums[64];
__device__ unsigned short g_csr16[cE];
__device__ float g_norm_out[cN];
__device__ float g_norm_in[cN];
__device__ short g_yq[(size_t)cN * cD];      // int16-quantized y = x@W1 (per-row scale)
__device__ float g_ysn[cN];                  // per-row scale * norm_out
__device__ float g_t[cN];
__device__ float g_u[cD];                    // u = W2 @ agg_w
__device__ float g_c;                        // c = b2 . agg_w + agg_b
__device__ float g_s[cN];
__device__ float g_v100[100];                // zeroed by k_final each call

__device__ __forceinline__ uint32_t f2tf32(float f) {
    uint32_t u;
    asm("cvt.rna.tf32.f32 %0, %1;" : "=r"(u) : "f"(f));
    return u;
}

// ---------------- launch 1: degree atomics || u = W2 @ agg_w ----------------
__global__ void k_fused_a(
    const int* __restrict__ src, const int* __restrict__ dst,
    const float* __restrict__ W2, const float* __restrict__ agg_w,
    const float* __restrict__ b2, const float* __restrict__ agg_b)
{
    int tid = threadIdx.x;
    if (blockIdx.x >= DEG_BLOCKS) {
        int gtid = (blockIdx.x - DEG_BLOCKS) * 256 + tid;
        int w = gtid >> 5, lane = gtid & 31;
        if (w < cD) {
            float sum = 0.f;
            #pragma unroll
            for (int c = lane; c < cD; c += 32) sum += W2[(size_t)w * cD + c] * agg_w[c];
            #pragma unroll
            for (int o = 16; o; o >>= 1) sum += __shfl_xor_sync(0xFFFFFFFFu, sum, o);
            if (lane == 0) g_u[w] = sum;
        } else if (w == cD) {
            float sum = 0.f;
            #pragma unroll
            for (int c = lane; c < cD; c += 32) sum += b2[c] * agg_w[c];
            #pragma unroll
            for (int o = 16; o; o >>= 1) sum += __shfl_xor_sync(0xFFFFFFFFu, sum, o);
            if (lane == 0) g_c = sum + agg_b[0];
        }
        return;
    }
    int i = blockIdx.x * 256 + tid;
    if (i < cE / 4) {
        int4 s = *(const int4*)&src[i * 4];
        int4 d = *(const int4*)&dst[i * 4];
        atomicAdd(&g_outdeg[s.x], 1); atomicAdd(&g_outdeg[s.y], 1);
        atomicAdd(&g_outdeg[s.z], 1); atomicAdd(&g_outdeg[s.w], 1);
        atomicAdd(&g_indeg[d.x], 1);  atomicAdd(&g_indeg[d.y], 1);
        atomicAdd(&g_indeg[d.z], 1);  atomicAdd(&g_indeg[d.w], 1);
    }
}

// ---------------- scans (two-kernel, spin-free, proven) ----------------
__global__ void k_scan_block() {
    __shared__ int warp_sums[8];
    int t = threadIdx.x;
    int gid = blockIdx.x * 1024 + t * 4;
    int4 v = make_int4(0, 0, 0, 0);
    if (gid < cN) v = *(const int4*)&g_indeg[gid];
    int tsum = v.x + v.y + v.z + v.w;
    int lane = t & 31, w = t >> 5;
    int inc = tsum;
    #pragma unroll
    for (int o = 1; o < 32; o <<= 1) {
        int n = __shfl_up_sync(0xFFFFFFFFu, inc, o);
        if (lane >= o) inc += n;
    }
    if (lane == 31) warp_sums[w] = inc;
    __syncthreads();
    if (t < 32) {
        int ws = (t < 8) ? warp_sums[t] : 0;
        int wi = ws;
        #pragma unroll
        for (int o = 1; o < 8; o <<= 1) {
            int n = __shfl_up_sync(0xFFFFFFFFu, wi, o);
            if (t >= o) wi += n;
        }
        if (t < 8) warp_sums[t] = wi - ws;
        if (t == 7) g_blocksums[blockIdx.x] = wi;
    }
    __syncthreads();
    if (gid < cN) {
        int ex = warp_sums[w] + (inc - tsum);
        int4 o;
        o.x = ex;
        o.y = ex + v.x;
        o.z = ex + v.x + v.y;
        o.w = ex + v.x + v.y + v.z;
        *(int4*)&g_offsets[gid] = o;
    }
}

// block base + cursor + norms (vectorized). Base covers up to 64 prior blocks.
__global__ void k_scan_add() {
    __shared__ int s_base;
    if (threadIdx.x < 32) {
        int t = threadIdx.x;
        int v = 0;
        if (t      < blockIdx.x) v += g_blocksums[t];
        if (t + 32 < blockIdx.x) v += g_blocksums[t + 32];
        #pragma unroll
        for (int o = 16; o; o >>= 1) v += __shfl_xor_sync(0xFFFFFFFFu, v, o);
        if (t == 0) s_base = v;
    }
    __syncthreads();
    int gid = blockIdx.x * 1024 + threadIdx.x * 4;
    if (gid < cN) {
        int4 o = *(const int4*)&g_offsets[gid];
        o.x += s_base; o.y += s_base; o.z += s_base; o.w += s_base;
        *(int4*)&g_offsets[gid] = o;
        *(int4*)&g_cursor[gid] = o;
        int4 od = *(const int4*)&g_outdeg[gid];
        int4 id = *(const int4*)&g_indeg[gid];
        float4 no, ni;
        no.x = rsqrtf(fmaxf((float)od.x, 1.0f)); no.y = rsqrtf(fmaxf((float)od.y, 1.0f));
        no.z = rsqrtf(fmaxf((float)od.z, 1.0f)); no.w = rsqrtf(fmaxf((float)od.w, 1.0f));
        ni.x = rsqrtf(fmaxf((float)id.x, 1.0f)); ni.y = rsqrtf(fmaxf((float)id.y, 1.0f));
        ni.z = rsqrtf(fmaxf((float)id.z, 1.0f)); ni.w = rsqrtf(fmaxf((float)id.w, 1.0f));
        *(float4*)&g_norm_out[gid] = no;
        *(float4*)&g_norm_in[gid] = ni;
    }
    if (gid == 0) g_offsets[cN] = cE;
}

// ---------------- launch 4: csr_fill loopers (1/SM) || tf32 GEMM ----------------
// Blocks 0..147 = grid-stride csr loopers (land one-per-SM per classic LUT placement);
// blocks 148.. = GEMM. Each SM hosts 1 looper + 1 GEMM block (2 blocks/SM at 125 regs):
// LTS-atomic work runs concurrently with tensor work.
__global__ __launch_bounds__(256) void k_fused_c(
    const float* __restrict__ x, const float* __restrict__ W1,
    const int* __restrict__ src, const int* __restrict__ dst)
{
    __shared__ uint32_t As[128 * 36];
    __shared__ uint32_t Ws[32 * 132];
    int tid = threadIdx.x;

    if (blockIdx.x < CSR2_BLOCKS) {
        const int stride = CSR2_BLOCKS * 256;
        for (int g = blockIdx.x * 256 + tid; g < cE / 4; g += stride) {
            int4 s = ((const int4*)src)[g];
            int4 d = ((const int4*)dst)[g];
            int p0 = atomicAdd(&g_cursor[d.x], 1);
            int p1 = atomicAdd(&g_cursor[d.y], 1);
            int p2 = atomicAdd(&g_cursor[d.z], 1);
            int p3 = atomicAdd(&g_cursor[d.w], 1);
            g_csr16[p0] = (unsigned short)s.x;
            g_csr16[p1] = (unsigned short)s.y;
            g_csr16[p2] = (unsigned short)s.z;
            g_csr16[p3] = (unsigned short)s.w;
        }
        // recycle degree arrays for next call (dead after scan)
        for (int i = blockIdx.x * 256 + tid; i < cN; i += stride) {
            g_outdeg[i] = 0;
            g_indeg[i] = 0;
        }
        return;
    }

    // ---- GEMM part ----
    int wid = tid >> 5;
    int lane = tid & 31;
    int r0 = (blockIdx.x - CSR2_BLOCKS) * 128;

    float acc[16][4];
    #pragma unroll
    for (int nt = 0; nt < 16; nt++)
        #pragma unroll
        for (int j = 0; j < 4; j++) acc[nt][j] = 0.f;

    for (int k0 = 0; k0 < cD; k0 += 32) {
        #pragma unroll
        for (int i = 0; i < 4; i++) {
            int idx = tid + 256 * i;
            int row = idx >> 3, c4 = idx & 7;
            int gr = r0 + row;
            float4 v = make_float4(0.f, 0.f, 0.f, 0.f);
            if (gr < cN) v = *(const float4*)&x[(size_t)gr * cD + k0 + c4 * 4];
            uint32_t* p = &As[row * 36 + c4 * 4];
            p[0] = f2tf32(v.x); p[1] = f2tf32(v.y); p[2] = f2tf32(v.z); p[3] = f2tf32(v.w);
        }
        #pragma unroll
        for (int i = 0; i < 4; i++) {
            int idx = tid + 256 * i;
            int row = idx >> 5, c4 = idx & 31;
            float4 v = *(const float4*)&W1[(size_t)(k0 + row) * cD + c4 * 4];
            uint32_t* p = &Ws[row * 132 + c4 * 4];
            p[0] = f2tf32(v.x); p[1] = f2tf32(v.y); p[2] = f2tf32(v.z); p[3] = f2tf32(v.w);
        }
        __syncthreads();
        #pragma unroll
        for (int ks = 0; ks < 4; ks++) {
            int ar = wid * 16 + (lane >> 2);
            int ac = ks * 8 + (lane & 3);
            uint32_t a0 = As[ar * 36 + ac];
            uint32_t a1 = As[(ar + 8) * 36 + ac];
            uint32_t a2 = As[ar * 36 + ac + 4];
            uint32_t a3 = As[(ar + 8) * 36 + ac + 4];
            int bk = ks * 8 + (lane & 3);
            int bn0 = (lane >> 2);
            #pragma unroll
            for (int nt = 0; nt < 16; nt++) {
                uint32_t b0 = Ws[bk * 132 + nt * 8 + bn0];
                uint32_t b1 = Ws[(bk + 4) * 132 + nt * 8 + bn0];
                asm volatile(
                    "mma.sync.aligned.m16n8k8.row.col.f32.tf32.tf32.f32 "
                    "{%0,%1,%2,%3}, {%4,%5,%6,%7}, {%8,%9}, {%0,%1,%2,%3};"
                    : "+f"(acc[nt][0]), "+f"(acc[nt][1]), "+f"(acc[nt][2]), "+f"(acc[nt][3])
                    : "r"(a0), "r"(a1), "r"(a2), "r"(a3), "r"(b0), "r"(b1));
            }
        }
        __syncthreads();
    }

    // Epilogue: per-row absmax int16 quantization; scale folds norm_out (scan done).
    float m_lo = 0.f, m_hi = 0.f;
    #pragma unroll
    for (int nt = 0; nt < 16; nt++) {
        m_lo = fmaxf(m_lo, fmaxf(fabsf(acc[nt][0]), fabsf(acc[nt][1])));
        m_hi = fmaxf(m_hi, fmaxf(fabsf(acc[nt][2]), fabsf(acc[nt][3])));
    }
    m_lo = fmaxf(m_lo, __shfl_xor_sync(0xFFFFFFFFu, m_lo, 1));
    m_lo = fmaxf(m_lo, __shfl_xor_sync(0xFFFFFFFFu, m_lo, 2));
    m_hi = fmaxf(m_hi, __shfl_xor_sync(0xFFFFFFFFu, m_hi, 1));
    m_hi = fmaxf(m_hi, __shfl_xor_sync(0xFFFFFFFFu, m_hi, 2));

    int ra = r0 + wid * 16 + (lane >> 2);
    int rb = ra + 8;
    float inv_lo = m_lo > 0.f ? 32767.0f / m_lo : 0.f;
    float inv_hi = m_hi > 0.f ? 32767.0f / m_hi : 0.f;
    #pragma unroll
    for (int nt = 0; nt < 16; nt++) {
        int col = nt * 8 + 2 * (lane & 3);
        if (ra < cN) {
            short2 q;
            q.x = (short)__float2int_rn(acc[nt][0] * inv_lo);
            q.y = (short)__float2int_rn(acc[nt][1] * inv_lo);
            *(short2*)&g_yq[(size_t)ra * cD + col] = q;
        }
        if (rb < cN) {
            short2 q;
            q.x = (short)__float2int_rn(acc[nt][2] * inv_hi);
            q.y = (short)__float2int_rn(acc[nt][3] * inv_hi);
            *(short2*)&g_yq[(size_t)rb * cD + col] = q;
        }
    }
    if ((lane & 3) == 0) {
        if (ra < cN) g_ysn[ra] = m_lo * (1.0f / 32767.0f) * g_norm_out[ra];
        if (rb < cN) g_ysn[rb] = m_hi * (1.0f / 32767.0f) * g_norm_out[rb];
    }
}

// ---------------- fused layer1 agg + bias + leaky + dot(u) -> g_t ----------------
__global__ void k_agg_fused(const float* __restrict__ b1) {
    int gtid = blockIdx.x * blockDim.x + threadIdx.x;
    int node = gtid >> 5, lane = gtid & 31;
    if (node >= cN) return;
    const short4* __restrict__ Yq = (const short4*)g_yq;
    int beg = g_offsets[node];
    int end = g_offsets[node + 1];
    float4 acc = make_float4(0.f, 0.f, 0.f, 0.f);
    int e = beg;
    for (; e + 3 < end; e += 4) {
        int s0 = g_csr16[e], s1 = g_csr16[e + 1], s2 = g_csr16[e + 2], s3 = g_csr16[e + 3];
        float f0 = g_ysn[s0], f1 = g_ysn[s1], f2 = g_ysn[s2], f3 = g_ysn[s3];
        short4 v0 = Yq[(size_t)s0 * 32 + lane];
        short4 v1 = Yq[(size_t)s1 * 32 + lane];
        short4 v2 = Yq[(size_t)s2 * 32 + lane];
        short4 v3 = Yq[(size_t)s3 * 32 + lane];
        acc.x += f0 * (float)v0.x + f1 * (float)v1.x + f2 * (float)v2.x + f3 * (float)v3.x;
        acc.y += f0 * (float)v0.y + f1 * (float)v1.y + f2 * (float)v2.y + f3 * (float)v3.y;
        acc.z += f0 * (float)v0.z + f1 * (float)v1.z + f2 * (float)v2.z + f3 * (float)v3.z;
        acc.w += f0 * (float)v0.w + f1 * (float)v1.w + f2 * (float)v2.w + f3 * (float)v3.w;
    }
    for (; e < end; e++) {
        int s0 = g_csr16[e];
        float f0 = g_ysn[s0];
        short4 v0 = Yq[(size_t)s0 * 32 + lane];
        acc.x += f0 * (float)v0.x;
        acc.y += f0 * (float)v0.y;
        acc.z += f0 * (float)v0.z;
        acc.w += f0 * (float)v0.w;
    }
    float fi = g_norm_in[node];
    float4 bv = *(const float4*)&b1[lane * 4];
    float4 uv = *(const float4*)&g_u[lane * 4];
    float hx = acc.x * fi + bv.x; hx = hx >= 0.f ? hx : SLOPE * hx;
    float hy = acc.y * fi + bv.y; hy = hy >= 0.f ? hy : SLOPE * hy;
    float hz = acc.z * fi + bv.z; hz = hz >= 0.f ? hz : SLOPE * hz;
    float hw = acc.w * fi + bv.w; hw = hw >= 0.f ? hw : SLOPE * hw;
    float sum = hx * uv.x + hy * uv.y + hz * uv.z + hw * uv.w;
    #pragma unroll
    for (int o = 16; o; o >>= 1) sum += __shfl_xor_sync(0xFFFFFFFFu, sum, o);
    if (lane == 0) g_t[node] = sum * g_norm_out[node];
}

// ---------------- layer 2 (collapsed): scalar edge gather ----------------
__global__ void k_sgather() {
    int gtid = blockIdx.x * blockDim.x + threadIdx.x;
    int node = gtid >> 5, lane = gtid & 31;
    if (node >= cN) return;
    int beg = g_offsets[node];
    int end = g_offsets[node + 1];
    float sum = 0.f;
    for (int e = beg + lane; e < end; e += 32) sum += g_t[g_csr16[e]];
    #pragma unroll
    for (int o = 16; o; o >>= 1) sum += __shfl_xor_sync(0xFFFFFFFFu, sum, o);
    if (lane == 0) g_s[node] = sum * g_norm_in[node] + g_c;
}

// ---------------- head ----------------
__global__ void k_dense1(const float* __restrict__ d1_w) {
    int c = threadIdx.x;
    int rows_per_block = (cN + gridDim.x - 1) / gridDim.x;
    int r0 = blockIdx.x * rows_per_block;
    int r1 = r0 + rows_per_block; if (r1 > cN) r1 = cN;
    if (c < 100) {
        float sum = 0.f;
        for (int r = r0; r < r1; r++)
            sum += g_s[r] * d1_w[(size_t)r * 100 + c];
        atomicAdd(&g_v100[c], sum);
    }
}

__global__ void k_final(const float* __restrict__ d1_b,
                        const float* __restrict__ d2_w, const float* __restrict__ d2_b,
                        const float* __restrict__ d3_w, const float* __restrict__ d3_b,
                        float* __restrict__ out) {
    __shared__ float h100[100];
    __shared__ float h20[20];
    int t = threadIdx.x;
    if (t < 100) h100[t] = g_v100[t] + d1_b[t];
    __syncthreads();
    if (t < 100) g_v100[t] = 0.0f;   // recycle for next call
    if (t < 20) {
        float v = d2_b[t];
        #pragma unroll 4
        for (int c = 0; c < 100; c++) v += h100[c] * d2_w[c * 20 + t];
        h20[t] = v >= 0.f ? v : SLOPE * v;
    }
    __syncthreads();
    if (t < 10) {
        float o = d3_b[t];
        #pragma unroll
        for (int c = 0; c < 20; c++) o += h20[c] * d3_w[c * 10 + t];
        out[t] = o;
    }
}

// ---------------- launch ----------------
extern "C" void kernel_launch(void* const* d_in, const int* in_sizes, int n_in,
                              void* d_out, int out_size) {
    const float* x     = (const float*)d_in[0];
    const int*   src   = (const int*)d_in[1];
    const int*   dst   = (const int*)d_in[2];
    const float* W1    = (const float*)d_in[3];
    const float* b1    = (const float*)d_in[4];
    const float* W2    = (const float*)d_in[5];
    const float* b2    = (const float*)d_in[6];
    const float* agg_w = (const float*)d_in[7];
    const float* agg_b = (const float*)d_in[8];
    const float* d1_w  = (const float*)d_in[9];
    const float* d1_b  = (const float*)d_in[10];
    const float* d2_w  = (const float*)d_in[11];
    const float* d2_b  = (const float*)d_in[12];
    const float* d3_w  = (const float*)d_in[13];
    const float* d3_b  = (const float*)d_in[14];
    float* out = (float*)d_out;

    const int nb_scan = (cN + 1023) / 1024;           // 49
    const int warp_blocks = (cN * 32 + 255) / 256;    // 6250 (warp per node)

    k_fused_a<<<DEG_BLOCKS + U_BLOCKS, 256>>>(src, dst, W2, agg_w, b2, agg_b);
    k_scan_block<<<nb_scan, 256>>>();
    k_scan_add<<<nb_scan, 256>>>();
    k_fused_c<<<CSR2_BLOCKS + GEMM_BLOCKS, 256>>>(x, W1, src, dst);

    k_agg_fused<<<warp_blocks, 256>>>(b1);
    k_sgather<<<warp_blocks, 256>>>();

    k_dense1<<<512, 128>>>(d1_w);
    k_final<<<1, 128>>>(d1_b, d2_w, d2_b, d3_w, d3_b, out);
}

// round 17
// speedup vs baseline: 1.5282x; 1.5282x over previous
#include <cuda_runtime.h>
#include <cuda_bf16.h>
#include <cstddef>
#include <cstdint>

#define cN 50000
#define cE 1600000
#define cD 128
#define SLOPE 0.01f

#define GEMM_BLOCKS 391   // (cN + 127) / 128
#define DEG_BLOCKS 1563   // (cE/4 + 255) / 256
#define U_BLOCKS 17       // ((cD+1)*32 + 255) / 256

// ---------------- scratch (static device globals; no allocation) ----------------
__device__ int   g_outdeg[cN];      // zeroed by k_csr_fill each call (zero-init first call)
__device__ int   g_indeg[cN];
__device__ int   g_offsets[cN + 4]; // segment start per node (arbitrary disjoint layout)
__device__ int   g_offe[cN + 4];    // segment end per node
__device__ int   g_cursor[cN];
__device__ int   g_total;           // segment allocator; reset by k_csr_fill each call
__device__ unsigned short g_csr16[cE];
__device__ float g_norm_out[cN];
__device__ float g_norm_in[cN];
__device__ short g_yq[(size_t)cN * cD];      // int16-quantized y = x@W1 (per-row scale)
__device__ float g_ysn[cN];                  // scale; *= norm_out in k_alloc
__device__ float g_t[cN];
__device__ float g_u[cD];                    // u = W2 @ agg_w
__device__ float g_c;                        // c = b2 . agg_w + agg_b
__device__ float g_s[cN];
__device__ float g_v100[100];                // zeroed by k_final each call

__device__ __forceinline__ uint32_t f2tf32(float f) {
    uint32_t u;
    asm("cvt.rna.tf32.f32 %0, %1;" : "=r"(u) : "f"(f));
    return u;
}

// ---------------- launch 1: tf32 GEMM (y=x@W1) || degree atomics || u ----------------
// GEMM graph-independent (norm_out fold deferred to k_alloc); deg + u hide under it.
__global__ __launch_bounds__(256) void k_fused1(
    const float* __restrict__ x, const float* __restrict__ W1,
    const int* __restrict__ src, const int* __restrict__ dst,
    const float* __restrict__ W2, const float* __restrict__ agg_w,
    const float* __restrict__ b2, const float* __restrict__ agg_b)
{
    __shared__ uint32_t As[128 * 36];
    __shared__ uint32_t Ws[32 * 132];
    int tid = threadIdx.x;

    if (blockIdx.x >= GEMM_BLOCKS + DEG_BLOCKS) {
        // ---- u part ----
        int gtid = (blockIdx.x - GEMM_BLOCKS - DEG_BLOCKS) * 256 + tid;
        int w = gtid >> 5, lane = gtid & 31;
        if (w < cD) {
            float sum = 0.f;
            #pragma unroll
            for (int c = lane; c < cD; c += 32) sum += W2[(size_t)w * cD + c] * agg_w[c];
            #pragma unroll
            for (int o = 16; o; o >>= 1) sum += __shfl_xor_sync(0xFFFFFFFFu, sum, o);
            if (lane == 0) g_u[w] = sum;
        } else if (w == cD) {
            float sum = 0.f;
            #pragma unroll
            for (int c = lane; c < cD; c += 32) sum += b2[c] * agg_w[c];
            #pragma unroll
            for (int o = 16; o; o >>= 1) sum += __shfl_xor_sync(0xFFFFFFFFu, sum, o);
            if (lane == 0) g_c = sum + agg_b[0];
        }
        return;
    }

    if (blockIdx.x >= GEMM_BLOCKS) {
        // ---- degrees: 4 edges per thread, int4 loads (cE % 4 == 0) ----
        int i = (blockIdx.x - GEMM_BLOCKS) * 256 + tid;
        if (i < cE / 4) {
            int4 s = *(const int4*)&src[i * 4];
            int4 d = *(const int4*)&dst[i * 4];
            atomicAdd(&g_outdeg[s.x], 1); atomicAdd(&g_outdeg[s.y], 1);
            atomicAdd(&g_outdeg[s.z], 1); atomicAdd(&g_outdeg[s.w], 1);
            atomicAdd(&g_indeg[d.x], 1);  atomicAdd(&g_indeg[d.y], 1);
            atomicAdd(&g_indeg[d.z], 1);  atomicAdd(&g_indeg[d.w], 1);
        }
        return;
    }

    // ---- GEMM part ----
    int wid = tid >> 5;
    int lane = tid & 31;
    int r0 = blockIdx.x * 128;

    float acc[16][4];
    #pragma unroll
    for (int nt = 0; nt < 16; nt++)
        #pragma unroll
        for (int j = 0; j < 4; j++) acc[nt][j] = 0.f;

    for (int k0 = 0; k0 < cD; k0 += 32) {
        #pragma unroll
        for (int i = 0; i < 4; i++) {
            int idx = tid + 256 * i;
            int row = idx >> 3, c4 = idx & 7;
            int gr = r0 + row;
            float4 v = make_float4(0.f, 0.f, 0.f, 0.f);
            if (gr < cN) v = *(const float4*)&x[(size_t)gr * cD + k0 + c4 * 4];
            uint32_t* p = &As[row * 36 + c4 * 4];
            p[0] = f2tf32(v.x); p[1] = f2tf32(v.y); p[2] = f2tf32(v.z); p[3] = f2tf32(v.w);
        }
        #pragma unroll
        for (int i = 0; i < 4; i++) {
            int idx = tid + 256 * i;
            int row = idx >> 5, c4 = idx & 31;
            float4 v = *(const float4*)&W1[(size_t)(k0 + row) * cD + c4 * 4];
            uint32_t* p = &Ws[row * 132 + c4 * 4];
            p[0] = f2tf32(v.x); p[1] = f2tf32(v.y); p[2] = f2tf32(v.z); p[3] = f2tf32(v.w);
        }
        __syncthreads();
        #pragma unroll
        for (int ks = 0; ks < 4; ks++) {
            int ar = wid * 16 + (lane >> 2);
            int ac = ks * 8 + (lane & 3);
            uint32_t a0 = As[ar * 36 + ac];
            uint32_t a1 = As[(ar + 8) * 36 + ac];
            uint32_t a2 = As[ar * 36 + ac + 4];
            uint32_t a3 = As[(ar + 8) * 36 + ac + 4];
            int bk = ks * 8 + (lane & 3);
            int bn0 = (lane >> 2);
            #pragma unroll
            for (int nt = 0; nt < 16; nt++) {
                uint32_t b0 = Ws[bk * 132 + nt * 8 + bn0];
                uint32_t b1 = Ws[(bk + 4) * 132 + nt * 8 + bn0];
                asm volatile(
                    "mma.sync.aligned.m16n8k8.row.col.f32.tf32.tf32.f32 "
                    "{%0,%1,%2,%3}, {%4,%5,%6,%7}, {%8,%9}, {%0,%1,%2,%3};"
                    : "+f"(acc[nt][0]), "+f"(acc[nt][1]), "+f"(acc[nt][2]), "+f"(acc[nt][3])
                    : "r"(a0), "r"(a1), "r"(a2), "r"(a3), "r"(b0), "r"(b1));
            }
        }
        __syncthreads();
    }

    // Epilogue: per-row absmax int16 quantization; RAW scale (norm_out folded in k_alloc).
    float m_lo = 0.f, m_hi = 0.f;
    #pragma unroll
    for (int nt = 0; nt < 16; nt++) {
        m_lo = fmaxf(m_lo, fmaxf(fabsf(acc[nt][0]), fabsf(acc[nt][1])));
        m_hi = fmaxf(m_hi, fmaxf(fabsf(acc[nt][2]), fabsf(acc[nt][3])));
    }
    m_lo = fmaxf(m_lo, __shfl_xor_sync(0xFFFFFFFFu, m_lo, 1));
    m_lo = fmaxf(m_lo, __shfl_xor_sync(0xFFFFFFFFu, m_lo, 2));
    m_hi = fmaxf(m_hi, __shfl_xor_sync(0xFFFFFFFFu, m_hi, 1));
    m_hi = fmaxf(m_hi, __shfl_xor_sync(0xFFFFFFFFu, m_hi, 2));

    int ra = r0 + wid * 16 + (lane >> 2);
    int rb = ra + 8;
    float inv_lo = m_lo > 0.f ? 32767.0f / m_lo : 0.f;
    float inv_hi = m_hi > 0.f ? 32767.0f / m_hi : 0.f;
    #pragma unroll
    for (int nt = 0; nt < 16; nt++) {
        int col = nt * 8 + 2 * (lane & 3);
        if (ra < cN) {
            short2 q;
            q.x = (short)__float2int_rn(acc[nt][0] * inv_lo);
            q.y = (short)__float2int_rn(acc[nt][1] * inv_lo);
            *(short2*)&g_yq[(size_t)ra * cD + col] = q;
        }
        if (rb < cN) {
            short2 q;
            q.x = (short)__float2int_rn(acc[nt][2] * inv_hi);
            q.y = (short)__float2int_rn(acc[nt][3] * inv_hi);
            *(short2*)&g_yq[(size_t)rb * cD + col] = q;
        }
    }
    if ((lane & 3) == 0) {
        if (ra < cN) g_ysn[ra] = m_lo * (1.0f / 32767.0f);
        if (rb < cN) g_ysn[rb] = m_hi * (1.0f / 32767.0f);
    }
}

// ---------------- launch 2: segment allocation (atomic, no scan) + norms + fold ----
// Contiguous per-node CSR segments with ARBITRARY inter-node layout: block-local
// prefix + ONE atomicAdd on g_total per block. Spin-free, order-independent.
__global__ void k_alloc() {
    __shared__ int warp_sums[8];
    __shared__ int s_base;
    int t = threadIdx.x;
    int gid = blockIdx.x * 1024 + t * 4;
    int4 v = make_int4(0, 0, 0, 0);
    if (gid < cN) v = *(const int4*)&g_indeg[gid];
    int tsum = v.x + v.y + v.z + v.w;
    int lane = t & 31, w = t >> 5;
    int inc = tsum;
    #pragma unroll
    for (int o = 1; o < 32; o <<= 1) {
        int n = __shfl_up_sync(0xFFFFFFFFu, inc, o);
        if (lane >= o) inc += n;
    }
    if (lane == 31) warp_sums[w] = inc;
    __syncthreads();
    if (t < 32) {
        int ws = (t < 8) ? warp_sums[t] : 0;
        int wi = ws;
        #pragma unroll
        for (int o = 1; o < 8; o <<= 1) {
            int n = __shfl_up_sync(0xFFFFFFFFu, wi, o);
            if (t >= o) wi += n;
        }
        if (t < 8) warp_sums[t] = wi - ws;          // exclusive warp base
        if (t == 7) s_base = atomicAdd(&g_total, wi);  // block base (wi = block total)
    }
    __syncthreads();
    if (gid < cN) {
        int ex = s_base + warp_sums[w] + (inc - tsum);
        int4 o, e;
        o.x = ex;              e.x = o.x + v.x;
        o.y = e.x;             e.y = o.y + v.y;
        o.z = e.y;             e.z = o.z + v.z;
        o.w = e.z;             e.w = o.w + v.w;
        *(int4*)&g_offsets[gid] = o;
        *(int4*)&g_offe[gid] = e;
        *(int4*)&g_cursor[gid] = o;
        int4 od = *(const int4*)&g_outdeg[gid];
        float4 no, ni;
        no.x = rsqrtf(fmaxf((float)od.x, 1.0f)); no.y = rsqrtf(fmaxf((float)od.y, 1.0f));
        no.z = rsqrtf(fmaxf((float)od.z, 1.0f)); no.w = rsqrtf(fmaxf((float)od.w, 1.0f));
        ni.x = rsqrtf(fmaxf((float)v.x, 1.0f));  ni.y = rsqrtf(fmaxf((float)v.y, 1.0f));
        ni.z = rsqrtf(fmaxf((float)v.z, 1.0f));  ni.w = rsqrtf(fmaxf((float)v.w, 1.0f));
        *(float4*)&g_norm_out[gid] = no;
        *(float4*)&g_norm_in[gid] = ni;
        float4 ys = *(const float4*)&g_ysn[gid];
        ys.x *= no.x; ys.y *= no.y; ys.z *= no.z; ys.w *= no.w;
        *(float4*)&g_ysn[gid] = ys;
    }
}

// ---------------- launch 3: csr fill + recycle (deg arrays, allocator) ----------------
__global__ void k_csr_fill(const int* __restrict__ src, const int* __restrict__ dst) {
    int i = blockIdx.x * blockDim.x + threadIdx.x;
    if (i < cE) {
        int p = atomicAdd(&g_cursor[dst[i]], 1);
        g_csr16[p] = (unsigned short)src[i];
    }
    if (i < cN) {
        g_outdeg[i] = 0;
        g_indeg[i] = 0;
    }
    if (i == 0) g_total = 0;   // reset allocator for next call
}

// ---------------- launch 4: fused layer1 agg + bias + leaky + dot(u) -> g_t --------
__global__ void k_agg_fused(const float* __restrict__ b1) {
    int gtid = blockIdx.x * blockDim.x + threadIdx.x;
    int node = gtid >> 5, lane = gtid & 31;
    if (node >= cN) return;
    const short4* __restrict__ Yq = (const short4*)g_yq;
    int beg = g_offsets[node];
    int end = g_offe[node];
    float4 acc = make_float4(0.f, 0.f, 0.f, 0.f);
    int e = beg;
    for (; e + 3 < end; e += 4) {
        int s0 = g_csr16[e], s1 = g_csr16[e + 1], s2 = g_csr16[e + 2], s3 = g_csr16[e + 3];
        float f0 = g_ysn[s0], f1 = g_ysn[s1], f2 = g_ysn[s2], f3 = g_ysn[s3];
        short4 v0 = Yq[(size_t)s0 * 32 + lane];
        short4 v1 = Yq[(size_t)s1 * 32 + lane];
        short4 v2 = Yq[(size_t)s2 * 32 + lane];
        short4 v3 = Yq[(size_t)s3 * 32 + lane];
        acc.x += f0 * (float)v0.x + f1 * (float)v1.x + f2 * (float)v2.x + f3 * (float)v3.x;
        acc.y += f0 * (float)v0.y + f1 * (float)v1.y + f2 * (float)v2.y + f3 * (float)v3.y;
        acc.z += f0 * (float)v0.z + f1 * (float)v1.z + f2 * (float)v2.z + f3 * (float)v3.z;
        acc.w += f0 * (float)v0.w + f1 * (float)v1.w + f2 * (float)v2.w + f3 * (float)v3.w;
    }
    for (; e < end; e++) {
        int s0 = g_csr16[e];
        float f0 = g_ysn[s0];
        short4 v0 = Yq[(size_t)s0 * 32 + lane];
        acc.x += f0 * (float)v0.x;
        acc.y += f0 * (float)v0.y;
        acc.z += f0 * (float)v0.z;
        acc.w += f0 * (float)v0.w;
    }
    float fi = g_norm_in[node];
    float4 bv = *(const float4*)&b1[lane * 4];
    float4 uv = *(const float4*)&g_u[lane * 4];
    float hx = acc.x * fi + bv.x; hx = hx >= 0.f ? hx : SLOPE * hx;
    float hy = acc.y * fi + bv.y; hy = hy >= 0.f ? hy : SLOPE * hy;
    float hz = acc.z * fi + bv.z; hz = hz >= 0.f ? hz : SLOPE * hz;
    float hw = acc.w * fi + bv.w; hw = hw >= 0.f ? hw : SLOPE * hw;
    float sum = hx * uv.x + hy * uv.y + hz * uv.z + hw * uv.w;
    #pragma unroll
    for (int o = 16; o; o >>= 1) sum += __shfl_xor_sync(0xFFFFFFFFu, sum, o);
    if (lane == 0) g_t[node] = sum * g_norm_out[node];
}

// ---------------- launch 5: layer 2 (collapsed) scalar edge gather ----------------
__global__ void k_sgather() {
    int gtid = blockIdx.x * blockDim.x + threadIdx.x;
    int node = gtid >> 5, lane = gtid & 31;
    if (node >= cN) return;
    int beg = g_offsets[node];
    int end = g_offe[node];
    float sum = 0.f;
    for (int e = beg + lane; e < end; e += 32) sum += g_t[g_csr16[e]];
    #pragma unroll
    for (int o = 16; o; o >>= 1) sum += __shfl_xor_sync(0xFFFFFFFFu, sum, o);
    if (lane == 0) g_s[node] = sum * g_norm_in[node] + g_c;
}

// ---------------- head ----------------
__global__ void k_dense1(const float* __restrict__ d1_w) {
    int c = threadIdx.x;
    int rows_per_block = (cN + gridDim.x - 1) / gridDim.x;
    int r0 = blockIdx.x * rows_per_block;
    int r1 = r0 + rows_per_block; if (r1 > cN) r1 = cN;
    if (c < 100) {
        float sum = 0.f;
        for (int r = r0; r < r1; r++)
            sum += g_s[r] * d1_w[(size_t)r * 100 + c];
        atomicAdd(&g_v100[c], sum);
    }
}

__global__ void k_final(const float* __restrict__ d1_b,
                        const float* __restrict__ d2_w, const float* __restrict__ d2_b,
                        const float* __restrict__ d3_w, const float* __restrict__ d3_b,
                        float* __restrict__ out) {
    __shared__ float h100[100];
    __shared__ float h20[20];
    int t = threadIdx.x;
    if (t < 100) h100[t] = g_v100[t] + d1_b[t];
    __syncthreads();
    if (t < 100) g_v100[t] = 0.0f;   // recycle for next call
    if (t < 20) {
        float v = d2_b[t];
        #pragma unroll 4
        for (int c = 0; c < 100; c++) v += h100[c] * d2_w[c * 20 + t];
        h20[t] = v >= 0.f ? v : SLOPE * v;
    }
    __syncthreads();
    if (t < 10) {
        float o = d3_b[t];
        #pragma unroll
        for (int c = 0; c < 20; c++) o += h20[c] * d3_w[c * 10 + t];
        out[t] = o;
    }
}

// ---------------- launch ----------------
extern "C" void kernel_launch(void* const* d_in, const int* in_sizes, int n_in,
                              void* d_out, int out_size) {
    const float* x     = (const float*)d_in[0];
    const int*   src   = (const int*)d_in[1];
    const int*   dst   = (const int*)d_in[2];
    const float* W1    = (const float*)d_in[3];
    const float* b1    = (const float*)d_in[4];
    const float* W2    = (const float*)d_in[5];
    const float* b2    = (const float*)d_in[6];
    const float* agg_w = (const float*)d_in[7];
    const float* agg_b = (const float*)d_in[8];
    const float* d1_w  = (const float*)d_in[9];
    const float* d1_b  = (const float*)d_in[10];
    const float* d2_w  = (const float*)d_in[11];
    const float* d2_b  = (const float*)d_in[12];
    const float* d3_w  = (const float*)d_in[13];
    const float* d3_b  = (const float*)d_in[14];
    float* out = (float*)d_out;

    const int nb_alloc = (cN + 1023) / 1024;          // 49
    const int eb = (cE + 255) / 256;                  // 6250
    const int warp_blocks = (cN * 32 + 255) / 256;    // 6250 (warp per node)
    const int fused_blocks = GEMM_BLOCKS + DEG_BLOCKS + U_BLOCKS;  // 1971

    k_fused1<<<fused_blocks, 256>>>(x, W1, src, dst, W2, agg_w, b2, agg_b);
    k_alloc<<<nb_alloc, 256>>>();
    k_csr_fill<<<eb, 256>>>(src, dst);

    k_agg_fused<<<warp_blocks, 256>>>(b1);
    k_sgather<<<warp_blocks, 256>>>();

    k_dense1<<<512, 128>>>(d1_w);
    k_final<<<1, 128>>>(d1_b, d2_w, d2_b, d3_w, d3_b, out);
}